// round 2
// baseline (speedup 1.0000x reference)
#include <cuda_runtime.h>
#include <math.h>

// Problem constants
#define B    16
#define CIN  256
#define HH   56
#define WW   56
#define E    8
#define COUT 256
#define KK   3
#define HW   (HH*WW)                 // 3136
#define WPE  (COUT*CIN*KK*KK)        // 589824 elements per expert
#define BN_EPS 1e-5f

// Device scratch (allocation-free rule: static __device__ globals)
__device__ float g_pooled[B*CIN];          // 4096
__device__ float g_route[B*E];             // 128
__device__ float g_cw[(size_t)B*WPE];      // 151 MB

// ---------------------------------------------------------------------------
// Kernel 1: global average pool. One block per (b,c) plane.
// ---------------------------------------------------------------------------
__global__ void gap_kernel(const float* __restrict__ x) {
    int bc = blockIdx.x;                      // 0..B*CIN-1
    const float* p = x + (size_t)bc * HW;
    float s = 0.f;
    for (int i = threadIdx.x; i < HW; i += blockDim.x) s += p[i];
    __shared__ float red[8];
    for (int off = 16; off > 0; off >>= 1) s += __shfl_down_sync(0xffffffffu, s, off);
    int wid = threadIdx.x >> 5, lid = threadIdx.x & 31;
    if (lid == 0) red[wid] = s;
    __syncthreads();
    if (wid == 0) {
        s = (lid < (blockDim.x >> 5)) ? red[lid] : 0.f;
        for (int off = 4; off > 0; off >>= 1) s += __shfl_down_sync(0xffffffffu, s, off);
        if (lid == 0) g_pooled[bc] = s * (1.f / (float)HW);
    }
}

// ---------------------------------------------------------------------------
// Kernel 2: routing = sigmoid(pooled @ Wr^T + br). One block, 128 threads.
// ---------------------------------------------------------------------------
__global__ void routing_kernel(const float* __restrict__ rw,
                               const float* __restrict__ rb) {
    int t = threadIdx.x;               // 0..127
    if (t >= B*E) return;
    int b = t >> 3, e = t & 7;
    float s = rb[e];
    const float* pp = &g_pooled[b*CIN];
    const float* wp = &rw[e*CIN];
    #pragma unroll 8
    for (int i = 0; i < CIN; i++) s = fmaf(pp[i], wp[i], s);
    g_route[t] = 1.f / (1.f + expf(-s));
}

// ---------------------------------------------------------------------------
// Kernel 3: combine expert weights: cw[b] = sum_e r[b,e] * W[e]
// float4-vectorized: each thread owns 4 consecutive elements.
// ---------------------------------------------------------------------------
__global__ void combine_kernel(const float* __restrict__ kw) {
    __shared__ float r[B*E];
    if (threadIdx.x < B*E) r[threadIdx.x] = g_route[threadIdx.x];
    __syncthreads();
    int v = blockIdx.x * blockDim.x + threadIdx.x;   // float4 index
    if (v >= WPE/4) return;
    const float4* kw4 = (const float4*)kw;
    float4* cw4 = (float4*)g_cw;
    float4 w[E];
    #pragma unroll
    for (int e = 0; e < E; e++) w[e] = kw4[(size_t)e*(WPE/4) + v];
    #pragma unroll
    for (int b = 0; b < B; b++) {
        float4 s = make_float4(0.f, 0.f, 0.f, 0.f);
        #pragma unroll
        for (int e = 0; e < E; e++) {
            float rv = r[b*E + e];
            s.x = fmaf(rv, w[e].x, s.x);
            s.y = fmaf(rv, w[e].y, s.y);
            s.z = fmaf(rv, w[e].z, s.z);
            s.w = fmaf(rv, w[e].w, s.w);
        }
        cw4[(size_t)b*(WPE/4) + v] = s;
    }
}

// ---------------------------------------------------------------------------
// Kernel 4: per-sample 3x3 conv (pad 1) + BN + SiLU.
// Grid: (row tiles=14, co tiles=4, b=16). Block: 256 threads.
// CTA computes 64 co x (4 rows x 56 cols). Thread: 8 co x 7 px.
// ---------------------------------------------------------------------------
#define CO_TILE 64
#define ROW_TILE 4
#define CI_CHUNK 8
#define IN_W 58   // 56 + 2 pad cols

__global__ __launch_bounds__(256, 2)
void conv_kernel(const float* __restrict__ x,
                 const float* __restrict__ bn_gamma,
                 const float* __restrict__ bn_beta,
                 const float* __restrict__ bn_mean,
                 const float* __restrict__ bn_var,
                 float* __restrict__ out) {
    const int row0 = blockIdx.x * ROW_TILE;
    const int co0  = blockIdx.y * CO_TILE;
    const int b    = blockIdx.z;

    const int tid  = threadIdx.x;
    const int cog  = tid >> 5;            // warp id: 0..7
    const int lane = tid & 31;
    const int rowg = lane >> 3;           // 0..3
    const int colg = lane & 7;            // 0..7
    const int c0   = colg * 7;            // first output col

    __shared__ float s_in[CI_CHUNK * 6 * IN_W];    // 2784 floats
    __shared__ float s_w [CO_TILE * CI_CHUNK * 9]; // 4608 floats

    float acc[8][7];
    #pragma unroll
    for (int i = 0; i < 8; i++)
        #pragma unroll
        for (int j = 0; j < 7; j++) acc[i][j] = 0.f;

    const int cw_base = b * WPE + co0 * (CIN*9);
    const float* xb = x + (size_t)b * CIN * HW;

    for (int ci0 = 0; ci0 < CIN; ci0 += CI_CHUNK) {
        __syncthreads();
        // --- load input patch: CI_CHUNK x 6 rows x 58 cols, zero-padded ---
        for (int j = tid; j < CI_CHUNK * 6 * IN_W; j += 256) {
            int ci  = j / (6 * IN_W);
            int rem = j - ci * (6 * IN_W);
            int rr  = rem / IN_W;
            int cc  = rem - rr * IN_W;
            int gr  = row0 + rr - 1;
            int gc  = cc - 1;
            float v = 0.f;
            if ((unsigned)gr < HH && (unsigned)gc < WW)
                v = xb[(ci0 + ci) * HW + gr * WW + gc];
            s_in[j] = v;
        }
        // --- load weights: 64 co x 8 ci x 9 (contiguous per co in g_cw) ---
        for (int j = tid; j < CO_TILE * CI_CHUNK * 9; j += 256) {
            int co  = j / (CI_CHUNK * 9);
            int rem = j - co * (CI_CHUNK * 9);
            s_w[j] = g_cw[(size_t)(cw_base + co * (CIN*9) + ci0 * 9 + rem)];
        }
        __syncthreads();

        #pragma unroll
        for (int ci = 0; ci < CI_CHUNK; ci++) {
            #pragma unroll
            for (int kh = 0; kh < 3; kh++) {
                float iv[9];
                const float* ip = &s_in[(ci * 6 + rowg + kh) * IN_W + c0];
                #pragma unroll
                for (int p = 0; p < 9; p++) iv[p] = ip[p];
                #pragma unroll
                for (int co = 0; co < 8; co++) {
                    const float* wp = &s_w[((cog*8 + co) * CI_CHUNK + ci) * 9 + kh * 3];
                    float w0 = wp[0], w1 = wp[1], w2 = wp[2];
                    #pragma unroll
                    for (int p = 0; p < 7; p++) {
                        acc[co][p] = fmaf(iv[p],   w0,
                                     fmaf(iv[p+1], w1,
                                     fmaf(iv[p+2], w2, acc[co][p])));
                    }
                }
            }
        }
    }

    // --- epilogue: BN + SiLU, store ---
    const int orow = row0 + rowg;
    #pragma unroll
    for (int co = 0; co < 8; co++) {
        int c = co0 + cog * 8 + co;
        float inv = bn_gamma[c] * rsqrtf(bn_var[c] + BN_EPS);
        float sh  = bn_beta[c] - bn_mean[c] * inv;
        float* op = out + ((size_t)(b * COUT + c) * HH + orow) * WW + c0;
        #pragma unroll
        for (int p = 0; p < 7; p++) {
            float y = fmaf(acc[co][p], inv, sh);
            op[p] = y / (1.f + expf(-y));
        }
    }
}

// ---------------------------------------------------------------------------
extern "C" void kernel_launch(void* const* d_in, const int* in_sizes, int n_in,
                              void* d_out, int out_size) {
    const float* x        = (const float*)d_in[0];
    const float* rw       = (const float*)d_in[1];
    const float* rb       = (const float*)d_in[2];
    const float* kw       = (const float*)d_in[3];
    const float* bn_gamma = (const float*)d_in[4];
    const float* bn_beta  = (const float*)d_in[5];
    const float* bn_mean  = (const float*)d_in[6];
    const float* bn_var   = (const float*)d_in[7];
    float* out = (float*)d_out;

    gap_kernel<<<B*CIN, 256>>>(x);
    routing_kernel<<<1, 128>>>(rw, rb);
    combine_kernel<<<(WPE/4 + 255) / 256, 256>>>(kw);
    dim3 grid(HH / ROW_TILE, COUT / CO_TILE, B);   // (14, 4, 16)
    conv_kernel<<<grid, 256>>>(x, bn_gamma, bn_beta, bn_mean, bn_var, out);
}

// round 4
// speedup vs baseline: 2.6287x; 2.6287x over previous
#include <cuda_runtime.h>
#include <math.h>

// Problem constants
#define B    16
#define CIN  256
#define HH   56
#define WW   56
#define E    8
#define COUT 256
#define TAPS 9
#define HW   (HH*WW)                 // 3136
#define WPE  (COUT*CIN*TAPS)         // 589824 elements per expert
#define BN_EPS 1e-5f

// Conv tiling
#define CO_T 64      // co per CTA
#define RP   2       // output rows per CTA
#define CI_C 8       // ci chunk (== mma K)

// Device scratch (allocation-free rule)
__device__ float g_pooled[B*CIN];
__device__ float g_route[B*E];
__device__ float g_cw2[(size_t)B*TAPS*COUT*CIN];   // tap-major combined weights, 151 MB

// ---------------------------------------------------------------------------
__device__ __forceinline__ unsigned f2tf32(float f) {
    unsigned u;
    asm("cvt.rna.tf32.f32 %0, %1;" : "=r"(u) : "f"(f));
    return u;
}

__device__ __forceinline__ void mma8(float* c,
                                     unsigned a0, unsigned a1, unsigned a2, unsigned a3,
                                     unsigned b0, unsigned b1) {
    asm volatile("mma.sync.aligned.m16n8k8.row.col.f32.tf32.tf32.f32 "
                 "{%0,%1,%2,%3}, {%4,%5,%6,%7}, {%8,%9}, {%0,%1,%2,%3};"
                 : "+f"(c[0]), "+f"(c[1]), "+f"(c[2]), "+f"(c[3])
                 : "r"(a0), "r"(a1), "r"(a2), "r"(a3), "r"(b0), "r"(b1));
}

// ---------------------------------------------------------------------------
// Kernel 1: global average pool. One block per (b,c) plane.
// ---------------------------------------------------------------------------
__global__ void gap_kernel(const float* __restrict__ x) {
    int bc = blockIdx.x;
    const float* p = x + (size_t)bc * HW;
    float s = 0.f;
    for (int i = threadIdx.x; i < HW; i += blockDim.x) s += p[i];
    __shared__ float red[8];
    for (int off = 16; off > 0; off >>= 1) s += __shfl_down_sync(0xffffffffu, s, off);
    int wid = threadIdx.x >> 5, lid = threadIdx.x & 31;
    if (lid == 0) red[wid] = s;
    __syncthreads();
    if (wid == 0) {
        s = (lid < (blockDim.x >> 5)) ? red[lid] : 0.f;
        for (int off = 4; off > 0; off >>= 1) s += __shfl_down_sync(0xffffffffu, s, off);
        if (lid == 0) g_pooled[bc] = s * (1.f / (float)HW);
    }
}

// ---------------------------------------------------------------------------
// Kernel 2: routing = sigmoid(pooled @ Wr^T + br).
// ---------------------------------------------------------------------------
__global__ void routing_kernel(const float* __restrict__ rw,
                               const float* __restrict__ rb) {
    int t = threadIdx.x;
    if (t >= B*E) return;
    int b = t >> 3, e = t & 7;
    float s = rb[e];
    const float* pp = &g_pooled[b*CIN];
    const float* wp = &rw[e*CIN];
    #pragma unroll 8
    for (int i = 0; i < CIN; i++) s = fmaf(pp[i], wp[i], s);
    g_route[t] = 1.f / (1.f + expf(-s));
}

// ---------------------------------------------------------------------------
// Kernel 3: combine + transpose to tap-major: g_cw2[b][tap][co][ci]
// Grid: 256 blocks (o), 256 threads (i).
// ---------------------------------------------------------------------------
__global__ void combine_kernel(const float* __restrict__ kw) {
    __shared__ float r[B*E];
    if (threadIdx.x < B*E) r[threadIdx.x] = g_route[threadIdx.x];
    __syncthreads();
    int o = blockIdx.x;
    int i = threadIdx.x;
    #pragma unroll
    for (int t = 0; t < TAPS; t++) {
        float w[E];
        #pragma unroll
        for (int e = 0; e < E; e++)
            w[e] = kw[(((size_t)e*COUT + o)*CIN + i)*TAPS + t];
        #pragma unroll
        for (int b = 0; b < B; b++) {
            float s = 0.f;
            #pragma unroll
            for (int e = 0; e < E; e++) s = fmaf(r[b*E + e], w[e], s);
            g_cw2[(((size_t)b*TAPS + t)*COUT + o)*CIN + i] = s;
        }
    }
}

// ---------------------------------------------------------------------------
// Kernel 4: tf32 tensor-core implicit conv + BN + SiLU.
// CTA: (rowpair, co-tile 64, b). 256 threads = 8 warps: warpM=wid&3 (16 co),
// warpR=wid>>2 (output row). Each warp: 7 n8 tiles along the 56-col row.
// 9 tap-GEMMs per ci-chunk of 8; shifts folded into b-frag LDS addresses.
// ---------------------------------------------------------------------------
__global__ __launch_bounds__(256)
void conv_mma_kernel(const float* __restrict__ x,
                     const float* __restrict__ bn_gamma,
                     const float* __restrict__ bn_beta,
                     const float* __restrict__ bn_mean,
                     const float* __restrict__ bn_var,
                     float* __restrict__ out) {
    const int rowpair = blockIdx.x;            // 0..27
    const int co0     = blockIdx.y * CO_T;     // 0,64,128,192
    const int b       = blockIdx.z;
    const int row0    = rowpair * RP;

    const int tid  = threadIdx.x;
    const int lane = tid & 31;
    const int wid  = tid >> 5;
    const int warpM = wid & 3;        // which m16 group
    const int warpR = wid >> 2;       // which output row (0/1)
    const int tg   = lane & 3;        // k-group
    const int grp  = lane >> 2;       // 0..7

    __shared__ float s_in[CI_C * 4 * 58];      // [ci][4 rows][58 cols] tf32 bits
    __shared__ float s_w [TAPS * CO_T * CI_C]; // [tap][co64][ci8] tf32 bits

    float acc[7][4];
    #pragma unroll
    for (int j = 0; j < 7; j++)
        #pragma unroll
        for (int q = 0; q < 4; q++) acc[j][q] = 0.f;

    // input-load thread mapping: pair = (ci, rr), 8 threads sweep 58 cols
    const int pair = tid >> 3;          // 0..31
    const int lci  = pair >> 2;         // 0..7
    const int lrr  = pair & 3;          // 0..3
    const int lcc0 = tid & 7;
    const int gr   = row0 + lrr - 1;    // -1..56
    const bool rok = (unsigned)gr < HH;

    const float* xb = x + (size_t)b * CIN * HW;
    const float* wsrc = g_cw2 + (size_t)b * TAPS * COUT * CIN;

    for (int ci0 = 0; ci0 < CIN; ci0 += CI_C) {
        __syncthreads();
        // ---- input patch: 8 ci x 4 rows x 58 cols, zero-padded, tf32-rounded
        {
            const float* src = xb + (ci0 + lci) * HW + gr * WW;
            float* dst = s_in + (lci * 4 + lrr) * 58;
            #pragma unroll
            for (int k2 = 0; k2 < 8; k2++) {
                int cc = lcc0 + 8 * k2;
                if (cc < 58) {
                    int gc = cc - 1;
                    float v = (rok && (unsigned)gc < WW) ? src[gc] : 0.f;
                    dst[cc] = __uint_as_float(f2tf32(v));
                }
            }
        }
        // ---- weights: 9 taps x 64 co x 8 ci, tf32-rounded
        #pragma unroll
        for (int k2 = 0; k2 < 18; k2++) {
            int d   = tid + 256 * k2;
            int ci  = d & 7;
            int co  = (d >> 3) & 63;
            int tap = d >> 9;
            float v = wsrc[(size_t)tap * (COUT*CIN) + (co0 + co) * CIN + ci0 + ci];
            s_w[d] = __uint_as_float(f2tf32(v));
        }
        __syncthreads();

        // ---- 9 tap-GEMMs on this ci chunk
        #pragma unroll
        for (int kh = 0; kh < 3; kh++) {
            const float* bb = s_in + (warpR + kh) * 58 + grp;
            #pragma unroll
            for (int kw = 0; kw < 3; kw++) {
                const int t = kh * 3 + kw;
                const float* ab = s_w + (t * CO_T + warpM * 16) * CI_C;
                unsigned a0 = __float_as_uint(ab[grp * 8 + tg]);
                unsigned a1 = __float_as_uint(ab[(grp + 8) * 8 + tg]);
                unsigned a2 = __float_as_uint(ab[grp * 8 + tg + 4]);
                unsigned a3 = __float_as_uint(ab[(grp + 8) * 8 + tg + 4]);
                #pragma unroll
                for (int j = 0; j < 7; j++) {
                    unsigned b0 = __float_as_uint(bb[tg * 232 + j * 8 + kw]);
                    unsigned b1 = __float_as_uint(bb[(tg + 4) * 232 + j * 8 + kw]);
                    mma8(acc[j], a0, a1, a2, a3, b0, b1);
                }
            }
        }
    }

    // ---- epilogue: BN + SiLU, float2 stores
    const int c1 = co0 + warpM * 16 + grp;
    const int c2 = c1 + 8;
    const int orow = row0 + warpR;
    const float inv1 = bn_gamma[c1] * rsqrtf(bn_var[c1] + BN_EPS);
    const float sh1  = bn_beta[c1] - bn_mean[c1] * inv1;
    const float inv2 = bn_gamma[c2] * rsqrtf(bn_var[c2] + BN_EPS);
    const float sh2  = bn_beta[c2] - bn_mean[c2] * inv2;
    float* o1 = out + ((size_t)(b * COUT + c1) * HH + orow) * WW;
    float* o2 = out + ((size_t)(b * COUT + c2) * HH + orow) * WW;
    #pragma unroll
    for (int j = 0; j < 7; j++) {
        int col = j * 8 + 2 * tg;
        float y0 = fmaf(acc[j][0], inv1, sh1);
        float y1 = fmaf(acc[j][1], inv1, sh1);
        float y2 = fmaf(acc[j][2], inv2, sh2);
        float y3 = fmaf(acc[j][3], inv2, sh2);
        float2 r1 = make_float2(y0 / (1.f + expf(-y0)), y1 / (1.f + expf(-y1)));
        float2 r2 = make_float2(y2 / (1.f + expf(-y2)), y3 / (1.f + expf(-y3)));
        *(float2*)(o1 + col) = r1;
        *(float2*)(o2 + col) = r2;
    }
}

// ---------------------------------------------------------------------------
extern "C" void kernel_launch(void* const* d_in, const int* in_sizes, int n_in,
                              void* d_out, int out_size) {
    const float* x        = (const float*)d_in[0];
    const float* rw       = (const float*)d_in[1];
    const float* rb       = (const float*)d_in[2];
    const float* kw       = (const float*)d_in[3];
    const float* bn_gamma = (const float*)d_in[4];
    const float* bn_beta  = (const float*)d_in[5];
    const float* bn_mean  = (const float*)d_in[6];
    const float* bn_var   = (const float*)d_in[7];
    float* out = (float*)d_out;

    gap_kernel<<<B*CIN, 256>>>(x);
    routing_kernel<<<1, 128>>>(rw, rb);
    combine_kernel<<<COUT, CIN>>>(kw);
    dim3 grid(HH / RP, COUT / CO_T, B);        // (28, 4, 16)
    conv_mma_kernel<<<grid, 256>>>(x, bn_gamma, bn_beta, bn_mean, bn_var, out);
}

// round 7
// speedup vs baseline: 3.5400x; 1.3467x over previous
#include <cuda_runtime.h>
#include <math.h>

// Problem constants
#define B    16
#define CIN  256
#define HH   56
#define WW   56
#define E    8
#define COUT 256
#define TAPS 9
#define HW   (HH*WW)                 // 3136
#define BN_EPS 1e-5f

// Conv tiling
#define CO_T 64      // co per CTA (whole warp does all 64: 4 m16 tiles)
#define RP   4       // output rows per CTA (= warps per CTA)
#define CI_C 8       // ci chunk (== mma K)
#define ROWF 480     // floats per patch row in s_in (60 cols * 8)

// Device scratch (allocation-free rule)
__device__ float g_pooled[B*CIN];
__device__ float g_route[B*E];
__device__ float g_cw2[(size_t)B*TAPS*COUT*CIN];   // tap-major combined weights

// ---------------------------------------------------------------------------
__device__ __forceinline__ unsigned f2tf32(float f) {
    unsigned u;
    asm("cvt.rna.tf32.f32 %0, %1;" : "=r"(u) : "f"(f));
    return u;
}

__device__ __forceinline__ void mma8(float* c,
                                     unsigned a0, unsigned a1, unsigned a2, unsigned a3,
                                     unsigned b0, unsigned b1) {
    asm volatile("mma.sync.aligned.m16n8k8.row.col.f32.tf32.tf32.f32 "
                 "{%0,%1,%2,%3}, {%4,%5,%6,%7}, {%8,%9}, {%0,%1,%2,%3};"
                 : "+f"(c[0]), "+f"(c[1]), "+f"(c[2]), "+f"(c[3])
                 : "r"(a0), "r"(a1), "r"(a2), "r"(a3), "r"(b0), "r"(b1));
}

// ---------------------------------------------------------------------------
// Kernel 1: global average pool. One block per (b,c) plane.
// ---------------------------------------------------------------------------
__global__ void gap_kernel(const float* __restrict__ x) {
    int bc = blockIdx.x;
    const float* p = x + (size_t)bc * HW;
    float s = 0.f;
    for (int i = threadIdx.x; i < HW; i += blockDim.x) s += p[i];
    __shared__ float red[8];
    for (int off = 16; off > 0; off >>= 1) s += __shfl_down_sync(0xffffffffu, s, off);
    int wid = threadIdx.x >> 5, lid = threadIdx.x & 31;
    if (lid == 0) red[wid] = s;
    __syncthreads();
    if (wid == 0) {
        s = (lid < (blockDim.x >> 5)) ? red[lid] : 0.f;
        for (int off = 4; off > 0; off >>= 1) s += __shfl_down_sync(0xffffffffu, s, off);
        if (lid == 0) g_pooled[bc] = s * (1.f / (float)HW);
    }
}

// ---------------------------------------------------------------------------
// Kernel 2: routing = sigmoid(pooled @ Wr^T + br).
// ---------------------------------------------------------------------------
__global__ void routing_kernel(const float* __restrict__ rw,
                               const float* __restrict__ rb) {
    int t = threadIdx.x;
    if (t >= B*E) return;
    int b = t >> 3, e = t & 7;
    float s = rb[e];
    const float* pp = &g_pooled[b*CIN];
    const float* wp = &rw[e*CIN];
    #pragma unroll 8
    for (int i = 0; i < CIN; i++) s = fmaf(pp[i], wp[i], s);
    g_route[t] = 1.f / (1.f + expf(-s));
}

// ---------------------------------------------------------------------------
// Kernel 3: combine + transpose to tap-major: g_cw2[b][tap][co][ci]
// ---------------------------------------------------------------------------
__global__ void combine_kernel(const float* __restrict__ kw) {
    __shared__ float r[B*E];
    if (threadIdx.x < B*E) r[threadIdx.x] = g_route[threadIdx.x];
    __syncthreads();
    int o = blockIdx.x;
    int i = threadIdx.x;
    #pragma unroll
    for (int t = 0; t < TAPS; t++) {
        float w[E];
        #pragma unroll
        for (int e = 0; e < E; e++)
            w[e] = kw[(((size_t)e*COUT + o)*CIN + i)*TAPS + t];
        #pragma unroll
        for (int b = 0; b < B; b++) {
            float s = 0.f;
            #pragma unroll
            for (int e = 0; e < E; e++) s = fmaf(r[b*E + e], w[e], s);
            g_cw2[(((size_t)b*TAPS + t)*COUT + o)*CIN + i] = s;
        }
    }
}

// ---------------------------------------------------------------------------
// Kernel 4: tf32 tensor-core implicit conv + BN + SiLU.
// CTA: (row-quad, co-tile 64, b). 128 threads = 4 warps; warp w = output row w.
// Each warp computes all 64 co (4 m16 tiles) x 1 row x 56 cols (7 n8 tiles).
// s_w in mma-frag order  -> A-frags are one LDS.128 per (tap, tile).
// s_in ci-pair interleaved [row][col][slot] -> B-frags are one LDS.64.
// ---------------------------------------------------------------------------
__global__ __launch_bounds__(128)
void conv_mma_kernel(const float* __restrict__ x,
                     const float* __restrict__ bn_gamma,
                     const float* __restrict__ bn_beta,
                     const float* __restrict__ bn_mean,
                     const float* __restrict__ bn_var,
                     float* __restrict__ out) {
    const int row0 = blockIdx.x * RP;          // 0,4,...,52
    const int co0  = blockIdx.y * CO_T;        // 0,64,128,192
    const int b    = blockIdx.z;

    const int tid  = threadIdx.x;
    const int lane = tid & 31;
    const int wid  = tid >> 5;        // warp = output row within CTA (0..3)
    const int tg   = lane & 3;        // mma k-group
    const int grp  = lane >> 2;       // 0..7

    __shared__ float s_in[6 * ROWF];           // 6 rows x 60 cols x 8 (interleaved ci pairs)
    __shared__ float s_w [TAPS * 4 * 32 * 4];  // frag order: [tap][tile][lane][4]

    float acc[4][7][4];
    #pragma unroll
    for (int t = 0; t < 4; t++)
        #pragma unroll
        for (int j = 0; j < 7; j++)
            #pragma unroll
            for (int q = 0; q < 4; q++) acc[t][j][q] = 0.f;

    const float* xb   = x + (size_t)b * CIN * HW;
    const float* wsrc = g_cw2 + (size_t)b * TAPS * COUT * CIN;

    for (int ci0 = 0; ci0 < CIN; ci0 += CI_C) {
        __syncthreads();
        // ---- stage input patch: 6 rows x 58 cols x 8 ci, interleaved pairs
        // s_in[row*480 + col*8 + q], q=2*tg+half -> ci = tg + half*4
        for (int idx = tid; idx < 6 * 464; idx += 128) {
            int row = idx / 464;
            int p   = idx - row * 464;           // col*8 + q
            int col = p >> 3;
            int q   = p & 7;
            int ci  = ((q >> 1) & 3) | ((q & 1) << 2);
            int gr  = row0 + row - 1;
            int gc  = col - 1;
            float v = 0.f;
            if ((unsigned)gr < HH && (unsigned)gc < WW)
                v = xb[(ci0 + ci) * HW + gr * WW + gc];
            s_in[row * ROWF + p] = __uint_as_float(f2tf32(v));
        }
        // ---- stage weights in mma-frag order:
        // idx = ((tap*4+tile)*32 + grp*4+tg)*4 + slot
        // slot: 0->(co=tile*16+grp, ci=tg) 1->(+8,tg) 2->(grp,tg+4) 3->(+8,tg+4)
        #pragma unroll
        for (int k2 = 0; k2 < 36; k2++) {
            int idx  = tid + 128 * k2;
            int slot = idx & 3;
            int ltg  = (idx >> 2) & 3;
            int lgrp = (idx >> 4) & 7;
            int tt   = idx >> 7;                 // tap*4 + tile
            int tap  = tt >> 2;
            int tile = tt & 3;
            int co   = tile * 16 + (slot & 1) * 8 + lgrp;
            int ci   = ltg + ((slot >> 1) << 2);
            float v  = wsrc[(size_t)tap * (COUT*CIN) + (co0 + co) * CIN + ci0 + ci];
            s_w[idx] = __uint_as_float(f2tf32(v));
        }
        __syncthreads();

        // ---- 9 tap-GEMMs
        #pragma unroll
        for (int kh = 0; kh < 3; kh++) {
            const float* brow = s_in + (wid + kh) * ROWF + grp * 8 + tg * 2;
            #pragma unroll
            for (int kw3 = 0; kw3 < 3; kw3++) {
                const int tap = kh * 3 + kw3;
                float4 a[4];
                #pragma unroll
                for (int t = 0; t < 4; t++)
                    a[t] = *(const float4*)(s_w + (tap * 4 + t) * 128 + lane * 4);
                float2 bv[7];
                #pragma unroll
                for (int j = 0; j < 7; j++)
                    bv[j] = *(const float2*)(brow + (j * 8 + kw3) * 8);
                #pragma unroll
                for (int t = 0; t < 4; t++)
                    #pragma unroll
                    for (int j = 0; j < 7; j++)
                        mma8(acc[t][j],
                             __float_as_uint(a[t].x), __float_as_uint(a[t].y),
                             __float_as_uint(a[t].z), __float_as_uint(a[t].w),
                             __float_as_uint(bv[j].x), __float_as_uint(bv[j].y));
            }
        }
    }

    // ---- epilogue: BN + SiLU, float2 stores
    const int orow = row0 + wid;
    #pragma unroll
    for (int t = 0; t < 4; t++) {
        const int c1 = co0 + t * 16 + grp;
        const int c2 = c1 + 8;
        const float inv1 = bn_gamma[c1] * rsqrtf(bn_var[c1] + BN_EPS);
        const float sh1  = bn_beta[c1] - bn_mean[c1] * inv1;
        const float inv2 = bn_gamma[c2] * rsqrtf(bn_var[c2] + BN_EPS);
        const float sh2  = bn_beta[c2] - bn_mean[c2] * inv2;
        float* o1 = out + ((size_t)(b * COUT + c1) * HH + orow) * WW;
        float* o2 = out + ((size_t)(b * COUT + c2) * HH + orow) * WW;
        #pragma unroll
        for (int j = 0; j < 7; j++) {
            int col = j * 8 + 2 * tg;
            float y0 = fmaf(acc[t][j][0], inv1, sh1);
            float y1 = fmaf(acc[t][j][1], inv1, sh1);
            float y2 = fmaf(acc[t][j][2], inv2, sh2);
            float y3 = fmaf(acc[t][j][3], inv2, sh2);
            float2 r1 = make_float2(y0 / (1.f + expf(-y0)), y1 / (1.f + expf(-y1)));
            float2 r2 = make_float2(y2 / (1.f + expf(-y2)), y3 / (1.f + expf(-y3)));
            *(float2*)(o1 + col) = r1;
            *(float2*)(o2 + col) = r2;
        }
    }
}

// ---------------------------------------------------------------------------
extern "C" void kernel_launch(void* const* d_in, const int* in_sizes, int n_in,
                              void* d_out, int out_size) {
    const float* x        = (const float*)d_in[0];
    const float* rw       = (const float*)d_in[1];
    const float* rb       = (const float*)d_in[2];
    const float* kw       = (const float*)d_in[3];
    const float* bn_gamma = (const float*)d_in[4];
    const float* bn_beta  = (const float*)d_in[5];
    const float* bn_mean  = (const float*)d_in[6];
    const float* bn_var   = (const float*)d_in[7];
    float* out = (float*)d_out;

    gap_kernel<<<B*CIN, 256>>>(x);
    routing_kernel<<<1, 128>>>(rw, rb);
    combine_kernel<<<COUT, CIN>>>(kw);
    dim3 grid(HH / RP, COUT / CO_T, B);        // (14, 4, 16)
    conv_mma_kernel<<<grid, 128>>>(x, bn_gamma, bn_beta, bn_mean, bn_var, out);
}

// round 8
// speedup vs baseline: 4.9957x; 1.4112x over previous
#include <cuda_runtime.h>
#include <math.h>
#include <stdint.h>

// Problem constants
#define B    16
#define CIN  256
#define HH   56
#define WW   56
#define E    8
#define COUT 256
#define TAPS 9
#define HW   (HH*WW)                 // 3136
#define BN_EPS 1e-5f

// Conv tiling
#define CO_T 64       // co per CTA
#define RP   4        // output rows per CTA (= warps)
#define CI_C 8        // ci chunk (== mma K)
#define ROWF 480      // floats per patch row (60 cols * 8)
#define NCHUNK 32     // CIN / CI_C
#define NRQ    14     // HH / RP
#define CHUNK_IN 2880 // 6*480 floats per input chunk
#define CHUNK_W  4608 // 9*4*32*4 floats per weight chunk

// Device scratch (allocation-free rule)
__device__ float g_pooled[B*CIN];
__device__ float g_route[B*E];
// frag-order tf32 weights: [b][cot(4)][cic(32)][4608]
__device__ float g_cwf[(size_t)B*4*NCHUNK*CHUNK_W];
// interleaved tf32 input patches: [b][rq(14)][cic(32)][2880]
__device__ float g_xin[(size_t)B*NRQ*NCHUNK*CHUNK_IN];

// ---------------------------------------------------------------------------
__device__ __forceinline__ unsigned f2tf32(float f) {
    unsigned u;
    asm("cvt.rna.tf32.f32 %0, %1;" : "=r"(u) : "f"(f));
    return u;
}

__device__ __forceinline__ void mma8(float* c,
                                     unsigned a0, unsigned a1, unsigned a2, unsigned a3,
                                     unsigned b0, unsigned b1) {
    asm volatile("mma.sync.aligned.m16n8k8.row.col.f32.tf32.tf32.f32 "
                 "{%0,%1,%2,%3}, {%4,%5,%6,%7}, {%8,%9}, {%0,%1,%2,%3};"
                 : "+f"(c[0]), "+f"(c[1]), "+f"(c[2]), "+f"(c[3])
                 : "r"(a0), "r"(a1), "r"(a2), "r"(a3), "r"(b0), "r"(b1));
}

__device__ __forceinline__ unsigned smem_u32(const void* p) {
    unsigned a;
    asm("{ .reg .u64 t; cvta.to.shared.u64 t, %1; cvt.u32.u64 %0, t; }"
        : "=r"(a) : "l"(p));
    return a;
}

__device__ __forceinline__ void cpa16(unsigned s, const void* g) {
    asm volatile("cp.async.cg.shared.global [%0], [%1], 16;" :: "r"(s), "l"(g));
}

// ---------------------------------------------------------------------------
// Kernel 1: global average pool.
// ---------------------------------------------------------------------------
__global__ void gap_kernel(const float* __restrict__ x) {
    int bc = blockIdx.x;
    const float* p = x + (size_t)bc * HW;
    float s = 0.f;
    for (int i = threadIdx.x; i < HW; i += blockDim.x) s += p[i];
    __shared__ float red[8];
    for (int off = 16; off > 0; off >>= 1) s += __shfl_down_sync(0xffffffffu, s, off);
    int wid = threadIdx.x >> 5, lid = threadIdx.x & 31;
    if (lid == 0) red[wid] = s;
    __syncthreads();
    if (wid == 0) {
        s = (lid < (blockDim.x >> 5)) ? red[lid] : 0.f;
        for (int off = 4; off > 0; off >>= 1) s += __shfl_down_sync(0xffffffffu, s, off);
        if (lid == 0) g_pooled[bc] = s * (1.f / (float)HW);
    }
}

// ---------------------------------------------------------------------------
// Kernel 2: routing = sigmoid(pooled @ Wr^T + br).
// ---------------------------------------------------------------------------
__global__ void routing_kernel(const float* __restrict__ rw,
                               const float* __restrict__ rb) {
    int t = threadIdx.x;
    if (t >= B*E) return;
    int b = t >> 3, e = t & 7;
    float s = rb[e];
    const float* pp = &g_pooled[b*CIN];
    const float* wp = &rw[e*CIN];
    #pragma unroll 8
    for (int i = 0; i < CIN; i++) s = fmaf(pp[i], wp[i], s);
    g_route[t] = 1.f / (1.f + expf(-s));
}

// ---------------------------------------------------------------------------
// Kernel 3: combine experts -> frag-order tf32 weights g_cwf.
// Grid (32 cic, 4 cot), 256 threads. Each thread: 18 frag positions x 16 b.
// frag idx = tap*512 + tile*128 + grp*16 + tg*4 + slot
//   co_l = tile*16 + (slot&1)*8 + grp ; ci_l = tg + (slot>>1)*4
// ---------------------------------------------------------------------------
__global__ void combine_kernel(const float* __restrict__ kw) {
    __shared__ float r[B*E];
    if (threadIdx.x < B*E) r[threadIdx.x] = g_route[threadIdx.x];
    __syncthreads();
    const int cic = blockIdx.x, cot = blockIdx.y;
    #pragma unroll
    for (int k = 0; k < 18; k++) {
        int idx  = threadIdx.x + 256 * k;
        int slot = idx & 3;
        int tg   = (idx >> 2) & 3;
        int grp  = (idx >> 4) & 7;
        int tile = (idx >> 7) & 3;
        int tap  = idx >> 9;
        int co   = cot * 64 + tile * 16 + (slot & 1) * 8 + grp;
        int ci   = cic * 8 + tg + ((slot >> 1) << 2);
        float w[E];
        #pragma unroll
        for (int e = 0; e < E; e++)
            w[e] = kw[(((size_t)e * COUT + co) * CIN + ci) * TAPS + tap];
        #pragma unroll
        for (int b = 0; b < B; b++) {
            float s = 0.f;
            #pragma unroll
            for (int e = 0; e < E; e++) s = fmaf(r[b*E + e], w[e], s);
            g_cwf[((size_t)(b * 4 + cot) * NCHUNK + cic) * CHUNK_W + idx] =
                __uint_as_float(f2tf32(s));
        }
    }
}

// ---------------------------------------------------------------------------
// Kernel 3b: input prep -> g_xin[b][rq][cic][6*480], zero-padded,
// ci-pair interleaved (q=2*tg+h -> ci = tg + 4h), tf32-rounded.
// Grid (14 rq, 32 cic, 16 b), 256 threads.
// ---------------------------------------------------------------------------
__global__ void prep_kernel(const float* __restrict__ x) {
    const int rq = blockIdx.x, cic = blockIdx.y, b = blockIdx.z;
    const float* xb = x + (size_t)b * CIN * HW;
    float* dst = g_xin + ((size_t)(b * NRQ + rq) * NCHUNK + cic) * CHUNK_IN;
    for (int i = threadIdx.x; i < CHUNK_IN; i += 256) {
        int row = i / ROWF;
        int p   = i - row * ROWF;
        int col = p >> 3;
        int q   = p & 7;
        int ci  = ((q >> 1) & 3) | ((q & 1) << 2);
        int gr  = rq * RP + row - 1;
        int gc  = col - 1;
        float v = 0.f;
        if ((unsigned)gr < HH && (unsigned)gc < WW)
            v = xb[(cic * 8 + ci) * HW + gr * WW + gc];
        dst[i] = __uint_as_float(f2tf32(v));
    }
}

// ---------------------------------------------------------------------------
// Kernel 4: tf32 tensor-core implicit conv + BN + SiLU.
// Double-buffered cp.async staging of preformatted chunks.
// CTA: (rq, cot, b), 128 threads = 4 warps; warp = output row.
// ---------------------------------------------------------------------------
__global__ __launch_bounds__(128, 3)
void conv_mma_kernel(const float* __restrict__ bn_gamma,
                     const float* __restrict__ bn_beta,
                     const float* __restrict__ bn_mean,
                     const float* __restrict__ bn_var,
                     float* __restrict__ out) {
    const int rq   = blockIdx.x;
    const int cot  = blockIdx.y;
    const int b    = blockIdx.z;
    const int co0  = cot * CO_T;
    const int row0 = rq * RP;

    const int tid  = threadIdx.x;
    const int lane = tid & 31;
    const int wid  = tid >> 5;
    const int tg   = lane & 3;
    const int grp  = lane >> 2;

    __shared__ __align__(16) float s_in[2][CHUNK_IN];
    __shared__ __align__(16) float s_w [2][CHUNK_W];

    const float* gin = g_xin + (size_t)(b * NRQ + rq) * NCHUNK * CHUNK_IN;
    const float* gw  = g_cwf + (size_t)(b * 4 + cot) * NCHUNK * CHUNK_W;

    float acc[4][7][4];
    #pragma unroll
    for (int t = 0; t < 4; t++)
        #pragma unroll
        for (int j = 0; j < 7; j++)
            #pragma unroll
            for (int q = 0; q < 4; q++) acc[t][j][q] = 0.f;

    // stage chunk c into buffer s (linear 16B copies)
    auto stage = [&](int c, int s) {
        unsigned din = smem_u32(&s_in[s][0]);
        unsigned dw  = smem_u32(&s_w[s][0]);
        const float* src_in = gin + (size_t)c * CHUNK_IN;
        const float* src_w  = gw  + (size_t)c * CHUNK_W;
        #pragma unroll
        for (int k = 0; k < 6; k++) {
            int i = tid + 128 * k;                 // float4 index, 720 total
            if (i < CHUNK_IN / 4)
                cpa16(din + 16u * i, src_in + 4 * i);
        }
        #pragma unroll
        for (int k = 0; k < 9; k++) {
            int i = tid + 128 * k;                 // 1152 total
            cpa16(dw + 16u * i, src_w + 4 * i);
        }
    };

    stage(0, 0);
    asm volatile("cp.async.commit_group;");

    for (int c = 0; c < NCHUNK; c++) {
        const int cur = c & 1;
        if (c + 1 < NCHUNK) stage(c + 1, cur ^ 1);
        asm volatile("cp.async.commit_group;");
        asm volatile("cp.async.wait_group 1;");
        __syncthreads();

        // ---- 9 tap-GEMMs on chunk c
        #pragma unroll
        for (int kh = 0; kh < 3; kh++) {
            const float* brow = &s_in[cur][(wid + kh) * ROWF + grp * 8 + tg * 2];
            #pragma unroll
            for (int kw3 = 0; kw3 < 3; kw3++) {
                const int tap = kh * 3 + kw3;
                float4 a[4];
                #pragma unroll
                for (int t = 0; t < 4; t++)
                    a[t] = *(const float4*)(&s_w[cur][(tap * 4 + t) * 128 + lane * 4]);
                float2 bv[7];
                #pragma unroll
                for (int j = 0; j < 7; j++)
                    bv[j] = *(const float2*)(brow + (j * 8 + kw3) * 8);
                #pragma unroll
                for (int t = 0; t < 4; t++)
                    #pragma unroll
                    for (int j = 0; j < 7; j++)
                        mma8(acc[t][j],
                             __float_as_uint(a[t].x), __float_as_uint(a[t].y),
                             __float_as_uint(a[t].z), __float_as_uint(a[t].w),
                             __float_as_uint(bv[j].x), __float_as_uint(bv[j].y));
            }
        }
        __syncthreads();
    }

    // ---- epilogue: BN + SiLU, float2 stores
    const int orow = row0 + wid;
    #pragma unroll
    for (int t = 0; t < 4; t++) {
        const int c1 = co0 + t * 16 + grp;
        const int c2 = c1 + 8;
        const float inv1 = bn_gamma[c1] * rsqrtf(bn_var[c1] + BN_EPS);
        const float sh1  = bn_beta[c1] - bn_mean[c1] * inv1;
        const float inv2 = bn_gamma[c2] * rsqrtf(bn_var[c2] + BN_EPS);
        const float sh2  = bn_beta[c2] - bn_mean[c2] * inv2;
        float* o1 = out + ((size_t)(b * COUT + c1) * HH + orow) * WW;
        float* o2 = out + ((size_t)(b * COUT + c2) * HH + orow) * WW;
        #pragma unroll
        for (int j = 0; j < 7; j++) {
            int col = j * 8 + 2 * tg;
            float y0 = fmaf(acc[t][j][0], inv1, sh1);
            float y1 = fmaf(acc[t][j][1], inv1, sh1);
            float y2 = fmaf(acc[t][j][2], inv2, sh2);
            float y3 = fmaf(acc[t][j][3], inv2, sh2);
            float2 r1 = make_float2(y0 / (1.f + expf(-y0)), y1 / (1.f + expf(-y1)));
            float2 r2 = make_float2(y2 / (1.f + expf(-y2)), y3 / (1.f + expf(-y3)));
            *(float2*)(o1 + col) = r1;
            *(float2*)(o2 + col) = r2;
        }
    }
}

// ---------------------------------------------------------------------------
extern "C" void kernel_launch(void* const* d_in, const int* in_sizes, int n_in,
                              void* d_out, int out_size) {
    const float* x        = (const float*)d_in[0];
    const float* rw       = (const float*)d_in[1];
    const float* rb       = (const float*)d_in[2];
    const float* kw       = (const float*)d_in[3];
    const float* bn_gamma = (const float*)d_in[4];
    const float* bn_beta  = (const float*)d_in[5];
    const float* bn_mean  = (const float*)d_in[6];
    const float* bn_var   = (const float*)d_in[7];
    float* out = (float*)d_out;

    prep_kernel<<<dim3(NRQ, NCHUNK, B), 256>>>(x);
    gap_kernel<<<B*CIN, 256>>>(x);
    routing_kernel<<<1, 128>>>(rw, rb);
    combine_kernel<<<dim3(NCHUNK, 4), 256>>>(kw);
    dim3 grid(NRQ, 4, B);                      // (14, 4, 16)
    conv_mma_kernel<<<grid, 128>>>(bn_gamma, bn_beta, bn_mean, bn_var, out);
}

// round 10
// speedup vs baseline: 7.3112x; 1.4635x over previous
#include <cuda_runtime.h>
#include <cuda_fp16.h>
#include <math.h>
#include <stdint.h>

// Problem constants
#define B    16
#define CIN  256
#define HH   56
#define WW   56
#define E    8
#define COUT 256
#define TAPS 9
#define HW   (HH*WW)                 // 3136
#define BN_EPS 1e-5f

// Conv tiling (fp16, K=16 per mma)
#define CO_T 64        // co per CTA
#define RP   4         // output rows per CTA (= warps)
#define CI_C 16        // ci chunk (== mma K)
#define NCHUNK 16      // CIN / CI_C
#define NRQ    14      // HH / RP
#define ROWU 480       // uint32 per patch row (60 cols * 8 slots)
#define CHUNK_IN 2880  // 6*480 uint32 per input chunk  (11520 B)
#define CHUNK_W  4608  // 9*4*32*4 uint32 per weight chunk (18432 B)

// Device scratch (allocation-free rule)
__device__ float g_pooled[B*CIN];
__device__ float g_route[B*E];
// frag-order fp16 weights: [b][cot(4)][cic(16)][4608 u32]
__device__ unsigned g_cwf[(size_t)B*4*NCHUNK*CHUNK_W];
// interleaved fp16 input patches: [b][rq(14)][cic(16)][2880 u32]
__device__ unsigned g_xin[(size_t)B*NRQ*NCHUNK*CHUNK_IN];

// ---------------------------------------------------------------------------
__device__ __forceinline__ void mma16(float* c, uint4 a, uint2 b) {
    asm volatile("mma.sync.aligned.m16n8k16.row.col.f32.f16.f16.f32 "
                 "{%0,%1,%2,%3}, {%4,%5,%6,%7}, {%8,%9}, {%0,%1,%2,%3};"
                 : "+f"(c[0]), "+f"(c[1]), "+f"(c[2]), "+f"(c[3])
                 : "r"(a.x), "r"(a.y), "r"(a.z), "r"(a.w), "r"(b.x), "r"(b.y));
}

__device__ __forceinline__ unsigned smem_u32(const void* p) {
    unsigned a;
    asm("{ .reg .u64 t; cvta.to.shared.u64 t, %1; cvt.u32.u64 %0, t; }"
        : "=r"(a) : "l"(p));
    return a;
}

__device__ __forceinline__ void cpa16(unsigned s, const void* g) {
    asm volatile("cp.async.cg.shared.global [%0], [%1], 16;" :: "r"(s), "l"(g));
}

// ---------------------------------------------------------------------------
// Kernel 1: global average pool.
// ---------------------------------------------------------------------------
__global__ void gap_kernel(const float* __restrict__ x) {
    int bc = blockIdx.x;
    const float* p = x + (size_t)bc * HW;
    float s = 0.f;
    for (int i = threadIdx.x; i < HW; i += blockDim.x) s += p[i];
    __shared__ float red[8];
    for (int off = 16; off > 0; off >>= 1) s += __shfl_down_sync(0xffffffffu, s, off);
    int wid = threadIdx.x >> 5, lid = threadIdx.x & 31;
    if (lid == 0) red[wid] = s;
    __syncthreads();
    if (wid == 0) {
        s = (lid < (blockDim.x >> 5)) ? red[lid] : 0.f;
        for (int off = 4; off > 0; off >>= 1) s += __shfl_down_sync(0xffffffffu, s, off);
        if (lid == 0) g_pooled[bc] = s * (1.f / (float)HW);
    }
}

// ---------------------------------------------------------------------------
// Kernel 2: routing = sigmoid(pooled @ Wr^T + br).
// ---------------------------------------------------------------------------
__global__ void routing_kernel(const float* __restrict__ rw,
                               const float* __restrict__ rb) {
    int t = threadIdx.x;
    if (t >= B*E) return;
    int b = t >> 3, e = t & 7;
    float s = rb[e];
    const float* pp = &g_pooled[b*CIN];
    const float* wp = &rw[e*CIN];
    #pragma unroll 8
    for (int i = 0; i < CIN; i++) s = fmaf(pp[i], wp[i], s);
    g_route[t] = 1.f / (1.f + expf(-s));
}

// ---------------------------------------------------------------------------
// Kernel 3: combine experts -> frag-order fp16 weights g_cwf (half2 per reg).
// frag idx = tap*512 + tile*128 + (grp*4+tg)*4 + r
//   co = tile*16 + (r&1)*8 + grp ; ci = 2*tg + ((r>>1)&1)*8, pair {ci, ci+1}
// m16n8k16 A frag: r0={A[grp][2tg],A[grp][2tg+1]}, r1=rows+8,
//                  r2={A[grp][2tg+8],A[grp][2tg+9]}, r3=rows+8.
// ---------------------------------------------------------------------------
__global__ void combine_kernel(const float* __restrict__ kw) {
    __shared__ float r[B*E];
    if (threadIdx.x < B*E) r[threadIdx.x] = g_route[threadIdx.x];
    __syncthreads();
    const int cic = blockIdx.x;   // 0..15
    const int cot = blockIdx.y;   // 0..3
    #pragma unroll
    for (int k = 0; k < 18; k++) {
        int idx  = threadIdx.x + 256 * k;      // 0..4607
        int rr   = idx & 3;
        int tg   = (idx >> 2) & 3;
        int grp  = (idx >> 4) & 7;
        int tile = (idx >> 7) & 3;
        int tap  = idx >> 9;
        int co   = cot * 64 + tile * 16 + (rr & 1) * 8 + grp;
        int ci   = cic * CI_C + 2 * tg + ((rr >> 1) & 1) * 8;
        float w0[E], w1[E];
        #pragma unroll
        for (int e = 0; e < E; e++) {
            const float* base = kw + (((size_t)e * COUT + co) * CIN + ci) * TAPS + tap;
            w0[e] = base[0];
            w1[e] = base[TAPS];
        }
        #pragma unroll
        for (int b = 0; b < B; b++) {
            float s0 = 0.f, s1 = 0.f;
            #pragma unroll
            for (int e = 0; e < E; e++) {
                float rv = r[b*E + e];
                s0 = fmaf(rv, w0[e], s0);
                s1 = fmaf(rv, w1[e], s1);
            }
            __half2 h = __floats2half2_rn(s0, s1);  // low=ci, high=ci+1
            g_cwf[((size_t)(b * 4 + cot) * NCHUNK + cic) * CHUNK_W + idx] =
                *(unsigned*)&h;
        }
    }
}

// ---------------------------------------------------------------------------
// Kernel 3b: input prep -> g_xin[b][rq][cic][6*480], zero-padded, fp16,
// slot q = 2*tg+h -> ci pair {2tg+8h, 2tg+8h+1}. Smem transpose so both
// global reads and writes are coalesced.
// Grid (14 rq, 16 cic, 16 b), 256 threads.
// ---------------------------------------------------------------------------
__global__ void prep_kernel(const float* __restrict__ x) {
    const int rq = blockIdx.x, cic = blockIdx.y, b = blockIdx.z;
    const float* xb = x + (size_t)b * CIN * HW;
    __shared__ float s[CI_C * 6 * 61];           // padded stride 61

    // phase A: coalesced global reads
    for (int idx = threadIdx.x; idx < CI_C * 6 * 60; idx += 256) {
        int ci  = idx / 360;
        int rem = idx - ci * 360;
        int row = rem / 60;
        int col = rem - row * 60;
        int gr  = rq * RP + row - 1;
        int gc  = col - 1;
        float v = 0.f;
        if ((unsigned)gr < HH && (unsigned)gc < WW)
            v = xb[(cic * CI_C + ci) * HW + gr * WW + gc];
        s[(ci * 6 + row) * 61 + col] = v;
    }
    __syncthreads();

    // phase B: coalesced interleaved fp16 writes
    unsigned* dst = g_xin + ((size_t)(b * NRQ + rq) * NCHUNK + cic) * CHUNK_IN;
    for (int i = threadIdx.x; i < CHUNK_IN; i += 256) {
        int row = i / ROWU;
        int p   = i - row * ROWU;
        int col = p >> 3;
        int q   = p & 7;
        int ci0 = 2 * (q >> 1) + 8 * (q & 1);
        float f0 = s[((ci0    ) * 6 + row) * 61 + col];
        float f1 = s[((ci0 + 1) * 6 + row) * 61 + col];
        __half2 h = __floats2half2_rn(f0, f1);
        dst[i] = *(unsigned*)&h;
    }
}

// ---------------------------------------------------------------------------
// Kernel 4: fp16 tensor-core implicit conv + BN + SiLU.
// Double-buffered cp.async staging. CTA: (rq, cot, b), 128 thr = 4 warps.
// ---------------------------------------------------------------------------
__global__ __launch_bounds__(128, 3)
void conv_mma_kernel(const float* __restrict__ bn_gamma,
                     const float* __restrict__ bn_beta,
                     const float* __restrict__ bn_mean,
                     const float* __restrict__ bn_var,
                     float* __restrict__ out) {
    const int rq   = blockIdx.x;
    const int cot  = blockIdx.y;
    const int b    = blockIdx.z;
    const int co0  = cot * CO_T;
    const int row0 = rq * RP;

    const int tid  = threadIdx.x;
    const int lane = tid & 31;
    const int wid  = tid >> 5;
    const int tg   = lane & 3;
    const int grp  = lane >> 2;

    __shared__ __align__(16) unsigned s_in[2][CHUNK_IN];
    __shared__ __align__(16) unsigned s_w [2][CHUNK_W];

    const unsigned* gin = g_xin + (size_t)(b * NRQ + rq) * NCHUNK * CHUNK_IN;
    const unsigned* gw  = g_cwf + (size_t)(b * 4 + cot) * NCHUNK * CHUNK_W;

    float acc[4][7][4];
    #pragma unroll
    for (int t = 0; t < 4; t++)
        #pragma unroll
        for (int j = 0; j < 7; j++)
            #pragma unroll
            for (int q = 0; q < 4; q++) acc[t][j][q] = 0.f;

    auto stage = [&](int c, int sb) {
        unsigned din = smem_u32(&s_in[sb][0]);
        unsigned dw  = smem_u32(&s_w[sb][0]);
        const unsigned* src_in = gin + (size_t)c * CHUNK_IN;
        const unsigned* src_w  = gw  + (size_t)c * CHUNK_W;
        #pragma unroll
        for (int k = 0; k < 6; k++) {
            int i = tid + 128 * k;                 // 16B units, 720 total
            if (i < CHUNK_IN / 4)
                cpa16(din + 16u * i, src_in + 4 * i);
        }
        #pragma unroll
        for (int k = 0; k < 9; k++) {
            int i = tid + 128 * k;                 // 1152 total
            cpa16(dw + 16u * i, src_w + 4 * i);
        }
    };

    stage(0, 0);
    asm volatile("cp.async.commit_group;");

    for (int c = 0; c < NCHUNK; c++) {
        const int cur = c & 1;
        if (c + 1 < NCHUNK) stage(c + 1, cur ^ 1);
        asm volatile("cp.async.commit_group;");
        asm volatile("cp.async.wait_group 1;");
        __syncthreads();

        #pragma unroll
        for (int kh = 0; kh < 3; kh++) {
            const unsigned* brow = &s_in[cur][(wid + kh) * ROWU];
            #pragma unroll
            for (int kw3 = 0; kw3 < 3; kw3++) {
                const int tap = kh * 3 + kw3;
                uint4 a[4];
                #pragma unroll
                for (int t = 0; t < 4; t++)
                    a[t] = *(const uint4*)(&s_w[cur][(tap * 4 + t) * 128 + lane * 4]);
                uint2 bv[7];
                #pragma unroll
                for (int j = 0; j < 7; j++)
                    bv[j] = *(const uint2*)(&brow[(j * 8 + grp + kw3) * 8 + tg * 2]);
                #pragma unroll
                for (int t = 0; t < 4; t++)
                    #pragma unroll
                    for (int j = 0; j < 7; j++)
                        mma16(acc[t][j], a[t], bv[j]);
            }
        }
        __syncthreads();
    }

    // ---- epilogue: BN + SiLU, float2 stores
    const int orow = row0 + wid;
    #pragma unroll
    for (int t = 0; t < 4; t++) {
        const int c1 = co0 + t * 16 + grp;
        const int c2 = c1 + 8;
        const float inv1 = bn_gamma[c1] * rsqrtf(bn_var[c1] + BN_EPS);
        const float sh1  = bn_beta[c1] - bn_mean[c1] * inv1;
        const float inv2 = bn_gamma[c2] * rsqrtf(bn_var[c2] + BN_EPS);
        const float sh2  = bn_beta[c2] - bn_mean[c2] * inv2;
        float* o1 = out + ((size_t)(b * COUT + c1) * HH + orow) * WW;
        float* o2 = out + ((size_t)(b * COUT + c2) * HH + orow) * WW;
        #pragma unroll
        for (int j = 0; j < 7; j++) {
            int col = j * 8 + 2 * tg;
            float y0 = fmaf(acc[t][j][0], inv1, sh1);
            float y1 = fmaf(acc[t][j][1], inv1, sh1);
            float y2 = fmaf(acc[t][j][2], inv2, sh2);
            float y3 = fmaf(acc[t][j][3], inv2, sh2);
            float2 r1 = make_float2(y0 / (1.f + expf(-y0)), y1 / (1.f + expf(-y1)));
            float2 r2 = make_float2(y2 / (1.f + expf(-y2)), y3 / (1.f + expf(-y3)));
            *(float2*)(o1 + col) = r1;
            *(float2*)(o2 + col) = r2;
        }
    }
}

// ---------------------------------------------------------------------------
extern "C" void kernel_launch(void* const* d_in, const int* in_sizes, int n_in,
                              void* d_out, int out_size) {
    const float* x        = (const float*)d_in[0];
    const float* rw       = (const float*)d_in[1];
    const float* rb       = (const float*)d_in[2];
    const float* kw       = (const float*)d_in[3];
    const float* bn_gamma = (const float*)d_in[4];
    const float* bn_beta  = (const float*)d_in[5];
    const float* bn_mean  = (const float*)d_in[6];
    const float* bn_var   = (const float*)d_in[7];
    float* out = (float*)d_out;

    prep_kernel<<<dim3(NRQ, NCHUNK, B), 256>>>(x);
    gap_kernel<<<B*CIN, 256>>>(x);
    routing_kernel<<<1, 128>>>(rw, rb);
    combine_kernel<<<dim3(NCHUNK, 4), 256>>>(kw);
    dim3 grid(NRQ, 4, B);                      // (14, 4, 16)
    conv_mma_kernel<<<grid, 128>>>(bn_gamma, bn_beta, bn_mean, bn_var, out);
}

// round 11
// speedup vs baseline: 7.7666x; 1.0623x over previous
#include <cuda_runtime.h>
#include <cuda_fp16.h>
#include <math.h>
#include <stdint.h>

// Problem constants
#define B    16
#define CIN  256
#define HH   56
#define WW   56
#define E    8
#define COUT 256
#define TAPS 9
#define HW   (HH*WW)                 // 3136
#define BN_EPS 1e-5f

// Conv tiling (fp16, K=16 per mma)
#define CO_T 64        // co per CTA
#define RP   4         // output rows per CTA (= warps)
#define CI_C 16        // ci chunk (== mma K)
#define NCHUNK 16      // CIN / CI_C
#define NRQ    14      // HH / RP
#define ROWU 480       // uint32 per patch row (60 cols * 8 slots)
#define CHUNK_IN 2880  // 6*480 uint32 per input chunk  (11520 B)
#define CHUNK_W  4608  // 9*4*32*4 uint32 per weight chunk (18432 B)

// Device scratch (allocation-free rule)
__device__ float g_pooled[B*CIN];
__device__ float g_route[B*E];
// frag-order fp16 weights: [b][cot(4)][cic(16)][4608 u32]
__device__ unsigned g_cwf[(size_t)B*4*NCHUNK*CHUNK_W];
// interleaved fp16 input patches: [b][rq(14)][cic(16)][2880 u32]
__device__ unsigned g_xin[(size_t)B*NRQ*NCHUNK*CHUNK_IN];

// ---------------------------------------------------------------------------
__device__ __forceinline__ void mma16(float* c, uint4 a, uint2 b) {
    asm volatile("mma.sync.aligned.m16n8k16.row.col.f32.f16.f16.f32 "
                 "{%0,%1,%2,%3}, {%4,%5,%6,%7}, {%8,%9}, {%0,%1,%2,%3};"
                 : "+f"(c[0]), "+f"(c[1]), "+f"(c[2]), "+f"(c[3])
                 : "r"(a.x), "r"(a.y), "r"(a.z), "r"(a.w), "r"(b.x), "r"(b.y));
}

__device__ __forceinline__ unsigned smem_u32(const void* p) {
    unsigned a;
    asm("{ .reg .u64 t; cvta.to.shared.u64 t, %1; cvt.u32.u64 %0, t; }"
        : "=r"(a) : "l"(p));
    return a;
}

__device__ __forceinline__ void cpa16(unsigned s, const void* g) {
    asm volatile("cp.async.cg.shared.global [%0], [%1], 16;" :: "r"(s), "l"(g));
}

// ---------------------------------------------------------------------------
// Kernel 1: global average pool.
// ---------------------------------------------------------------------------
__global__ void gap_kernel(const float* __restrict__ x) {
    int bc = blockIdx.x;
    const float* p = x + (size_t)bc * HW;
    float s = 0.f;
    for (int i = threadIdx.x; i < HW; i += blockDim.x) s += p[i];
    __shared__ float red[8];
    for (int off = 16; off > 0; off >>= 1) s += __shfl_down_sync(0xffffffffu, s, off);
    int wid = threadIdx.x >> 5, lid = threadIdx.x & 31;
    if (lid == 0) red[wid] = s;
    __syncthreads();
    if (wid == 0) {
        s = (lid < (blockDim.x >> 5)) ? red[lid] : 0.f;
        for (int off = 4; off > 0; off >>= 1) s += __shfl_down_sync(0xffffffffu, s, off);
        if (lid == 0) g_pooled[bc] = s * (1.f / (float)HW);
    }
}

// ---------------------------------------------------------------------------
// Kernel 2: routing = sigmoid(pooled @ Wr^T + br).
// ---------------------------------------------------------------------------
__global__ void routing_kernel(const float* __restrict__ rw,
                               const float* __restrict__ rb) {
    int t = threadIdx.x;
    if (t >= B*E) return;
    int b = t >> 3, e = t & 7;
    float s = rb[e];
    const float* pp = &g_pooled[b*CIN];
    const float* wp = &rw[e*CIN];
    #pragma unroll 8
    for (int i = 0; i < CIN; i++) s = fmaf(pp[i], wp[i], s);
    g_route[t] = 1.f / (1.f + expf(-s));
}

// ---------------------------------------------------------------------------
// Kernel 3: combine experts -> frag-order fp16 weights g_cwf (half2 per reg).
// frag idx = tap*512 + tile*128 + (grp*4+tg)*4 + r
//   co = tile*16 + (r&1)*8 + grp ; ci = 2*tg + ((r>>1)&1)*8, pair {ci, ci+1}
// Grid (16 cic, 4 cot, 6 kz): each block covers 3 of 18 frag strides ->
// 384 blocks, 6x the in-flight-load pool of R10 (was latency-bound at 64).
// ---------------------------------------------------------------------------
__global__ void combine_kernel(const float* __restrict__ kw) {
    __shared__ float r[B*E];
    if (threadIdx.x < B*E) r[threadIdx.x] = g_route[threadIdx.x];
    __syncthreads();
    const int cic = blockIdx.x;   // 0..15
    const int cot = blockIdx.y;   // 0..3
    const int kz  = blockIdx.z;   // 0..5
    #pragma unroll
    for (int k = 0; k < 3; k++) {
        int idx  = threadIdx.x + 256 * (kz * 3 + k);   // 0..4607
        int rr   = idx & 3;
        int tg   = (idx >> 2) & 3;
        int grp  = (idx >> 4) & 7;
        int tile = (idx >> 7) & 3;
        int tap  = idx >> 9;
        int co   = cot * 64 + tile * 16 + (rr & 1) * 8 + grp;
        int ci   = cic * CI_C + 2 * tg + ((rr >> 1) & 1) * 8;
        float w0[E], w1[E];
        #pragma unroll
        for (int e = 0; e < E; e++) {
            const float* base = kw + (((size_t)e * COUT + co) * CIN + ci) * TAPS + tap;
            w0[e] = base[0];
            w1[e] = base[TAPS];
        }
        #pragma unroll
        for (int b = 0; b < B; b++) {
            float s0 = 0.f, s1 = 0.f;
            #pragma unroll
            for (int e = 0; e < E; e++) {
                float rv = r[b*E + e];
                s0 = fmaf(rv, w0[e], s0);
                s1 = fmaf(rv, w1[e], s1);
            }
            __half2 h = __floats2half2_rn(s0, s1);  // low=ci, high=ci+1
            g_cwf[((size_t)(b * 4 + cot) * NCHUNK + cic) * CHUNK_W + idx] =
                *(unsigned*)&h;
        }
    }
}

// ---------------------------------------------------------------------------
// Kernel 3b: input prep -> g_xin[b][rq][cic][6*480], zero-padded, fp16,
// slot q = 2*tg+h -> ci pair {2tg+8h, 2tg+8h+1}. Smem transpose so both
// global reads and writes are coalesced.
// Grid (14 rq, 16 cic, 16 b), 256 threads.
// ---------------------------------------------------------------------------
__global__ void prep_kernel(const float* __restrict__ x) {
    const int rq = blockIdx.x, cic = blockIdx.y, b = blockIdx.z;
    const float* xb = x + (size_t)b * CIN * HW;
    __shared__ float s[CI_C * 6 * 61];           // padded stride 61

    // phase A: coalesced global reads
    for (int idx = threadIdx.x; idx < CI_C * 6 * 60; idx += 256) {
        int ci  = idx / 360;
        int rem = idx - ci * 360;
        int row = rem / 60;
        int col = rem - row * 60;
        int gr  = rq * RP + row - 1;
        int gc  = col - 1;
        float v = 0.f;
        if ((unsigned)gr < HH && (unsigned)gc < WW)
            v = xb[(cic * CI_C + ci) * HW + gr * WW + gc];
        s[(ci * 6 + row) * 61 + col] = v;
    }
    __syncthreads();

    // phase B: coalesced interleaved fp16 writes
    unsigned* dst = g_xin + ((size_t)(b * NRQ + rq) * NCHUNK + cic) * CHUNK_IN;
    for (int i = threadIdx.x; i < CHUNK_IN; i += 256) {
        int row = i / ROWU;
        int p   = i - row * ROWU;
        int col = p >> 3;
        int q   = p & 7;
        int ci0 = 2 * (q >> 1) + 8 * (q & 1);
        float f0 = s[((ci0    ) * 6 + row) * 61 + col];
        float f1 = s[((ci0 + 1) * 6 + row) * 61 + col];
        __half2 h = __floats2half2_rn(f0, f1);
        dst[i] = *(unsigned*)&h;
    }
}

// ---------------------------------------------------------------------------
// Kernel 4: fp16 tensor-core implicit conv + BN + SiLU.
// Double-buffered cp.async staging. CTA: (rq, cot, b), 128 thr = 4 warps.
// ---------------------------------------------------------------------------
__global__ __launch_bounds__(128, 3)
void conv_mma_kernel(const float* __restrict__ bn_gamma,
                     const float* __restrict__ bn_beta,
                     const float* __restrict__ bn_mean,
                     const float* __restrict__ bn_var,
                     float* __restrict__ out) {
    const int rq   = blockIdx.x;
    const int cot  = blockIdx.y;
    const int b    = blockIdx.z;
    const int co0  = cot * CO_T;
    const int row0 = rq * RP;

    const int tid  = threadIdx.x;
    const int lane = tid & 31;
    const int wid  = tid >> 5;
    const int tg   = lane & 3;
    const int grp  = lane >> 2;

    __shared__ __align__(16) unsigned s_in[2][CHUNK_IN];
    __shared__ __align__(16) unsigned s_w [2][CHUNK_W];

    const unsigned* gin = g_xin + (size_t)(b * NRQ + rq) * NCHUNK * CHUNK_IN;
    const unsigned* gw  = g_cwf + (size_t)(b * 4 + cot) * NCHUNK * CHUNK_W;

    float acc[4][7][4];
    #pragma unroll
    for (int t = 0; t < 4; t++)
        #pragma unroll
        for (int j = 0; j < 7; j++)
            #pragma unroll
            for (int q = 0; q < 4; q++) acc[t][j][q] = 0.f;

    auto stage = [&](int c, int sb) {
        unsigned din = smem_u32(&s_in[sb][0]);
        unsigned dw  = smem_u32(&s_w[sb][0]);
        const unsigned* src_in = gin + (size_t)c * CHUNK_IN;
        const unsigned* src_w  = gw  + (size_t)c * CHUNK_W;
        #pragma unroll
        for (int k = 0; k < 6; k++) {
            int i = tid + 128 * k;                 // 16B units, 720 total
            if (i < CHUNK_IN / 4)
                cpa16(din + 16u * i, src_in + 4 * i);
        }
        #pragma unroll
        for (int k = 0; k < 9; k++) {
            int i = tid + 128 * k;                 // 1152 total
            cpa16(dw + 16u * i, src_w + 4 * i);
        }
    };

    stage(0, 0);
    asm volatile("cp.async.commit_group;");

    for (int c = 0; c < NCHUNK; c++) {
        const int cur = c & 1;
        if (c + 1 < NCHUNK) stage(c + 1, cur ^ 1);
        asm volatile("cp.async.commit_group;");
        asm volatile("cp.async.wait_group 1;");
        __syncthreads();

        #pragma unroll
        for (int kh = 0; kh < 3; kh++) {
            const unsigned* brow = &s_in[cur][(wid + kh) * ROWU];
            #pragma unroll
            for (int kw3 = 0; kw3 < 3; kw3++) {
                const int tap = kh * 3 + kw3;
                uint4 a[4];
                #pragma unroll
                for (int t = 0; t < 4; t++)
                    a[t] = *(const uint4*)(&s_w[cur][(tap * 4 + t) * 128 + lane * 4]);
                uint2 bv[7];
                #pragma unroll
                for (int j = 0; j < 7; j++)
                    bv[j] = *(const uint2*)(&brow[(j * 8 + grp + kw3) * 8 + tg * 2]);
                #pragma unroll
                for (int t = 0; t < 4; t++)
                    #pragma unroll
                    for (int j = 0; j < 7; j++)
                        mma16(acc[t][j], a[t], bv[j]);
            }
        }
        __syncthreads();
    }

    // ---- epilogue: BN + SiLU, float2 stores
    const int orow = row0 + wid;
    #pragma unroll
    for (int t = 0; t < 4; t++) {
        const int c1 = co0 + t * 16 + grp;
        const int c2 = c1 + 8;
        const float inv1 = bn_gamma[c1] * rsqrtf(bn_var[c1] + BN_EPS);
        const float sh1  = bn_beta[c1] - bn_mean[c1] * inv1;
        const float inv2 = bn_gamma[c2] * rsqrtf(bn_var[c2] + BN_EPS);
        const float sh2  = bn_beta[c2] - bn_mean[c2] * inv2;
        float* o1 = out + ((size_t)(b * COUT + c1) * HH + orow) * WW;
        float* o2 = out + ((size_t)(b * COUT + c2) * HH + orow) * WW;
        #pragma unroll
        for (int j = 0; j < 7; j++) {
            int col = j * 8 + 2 * tg;
            float y0 = fmaf(acc[t][j][0], inv1, sh1);
            float y1 = fmaf(acc[t][j][1], inv1, sh1);
            float y2 = fmaf(acc[t][j][2], inv2, sh2);
            float y3 = fmaf(acc[t][j][3], inv2, sh2);
            float2 r1 = make_float2(y0 / (1.f + expf(-y0)), y1 / (1.f + expf(-y1)));
            float2 r2 = make_float2(y2 / (1.f + expf(-y2)), y3 / (1.f + expf(-y3)));
            *(float2*)(o1 + col) = r1;
            *(float2*)(o2 + col) = r2;
        }
    }
}

// ---------------------------------------------------------------------------
extern "C" void kernel_launch(void* const* d_in, const int* in_sizes, int n_in,
                              void* d_out, int out_size) {
    const float* x        = (const float*)d_in[0];
    const float* rw       = (const float*)d_in[1];
    const float* rb       = (const float*)d_in[2];
    const float* kw       = (const float*)d_in[3];
    const float* bn_gamma = (const float*)d_in[4];
    const float* bn_beta  = (const float*)d_in[5];
    const float* bn_mean  = (const float*)d_in[6];
    const float* bn_var   = (const float*)d_in[7];
    float* out = (float*)d_out;

    prep_kernel<<<dim3(NRQ, NCHUNK, B), 256>>>(x);
    gap_kernel<<<B*CIN, 256>>>(x);
    routing_kernel<<<1, 128>>>(rw, rb);
    combine_kernel<<<dim3(NCHUNK, 4, 6), 256>>>(kw);
    dim3 grid(NRQ, 4, B);                      // (14, 4, 16)
    conv_mma_kernel<<<grid, 128>>>(bn_gamma, bn_beta, bn_mean, bn_var, out);
}

// round 12
// speedup vs baseline: 7.8333x; 1.0086x over previous
#include <cuda_runtime.h>
#include <cuda_fp16.h>
#include <math.h>
#include <stdint.h>

// Problem constants
#define B    16
#define CIN  256
#define HH   56
#define WW   56
#define E    8
#define COUT 256
#define TAPS 9
#define HW   (HH*WW)                 // 3136
#define BN_EPS 1e-5f

// Conv tiling (fp16, K=16 per mma)
#define CO_T 64        // co per CTA
#define RP   4         // output rows per CTA (= warps)
#define CI_C 16        // ci chunk (== mma K)
#define NCHUNK 16      // CIN / CI_C
#define NRQ    14      // HH / RP
#define ROWU 480       // uint32 per patch row (60 cols * 8 slots)
#define CHUNK_IN 2880  // 6*480 uint32 per input chunk  (11520 B)
#define CHUNK_W  4608  // 9*4*32*4 uint32 per weight chunk (18432 B)

// Device scratch (allocation-free rule)
__device__ float g_pooled[B*CIN];
__device__ float g_route[B*E];
// frag-order fp16 weights: [b][cot(4)][cic(16)][4608 u32]
__device__ unsigned g_cwf[(size_t)B*4*NCHUNK*CHUNK_W];
// interleaved fp16 input patches: [b][rq(14)][cic(16)][2880 u32]
__device__ unsigned g_xin[(size_t)B*NRQ*NCHUNK*CHUNK_IN];

// ---------------------------------------------------------------------------
__device__ __forceinline__ void mma16(float* c, uint4 a, uint2 b) {
    asm volatile("mma.sync.aligned.m16n8k16.row.col.f32.f16.f16.f32 "
                 "{%0,%1,%2,%3}, {%4,%5,%6,%7}, {%8,%9}, {%0,%1,%2,%3};"
                 : "+f"(c[0]), "+f"(c[1]), "+f"(c[2]), "+f"(c[3])
                 : "r"(a.x), "r"(a.y), "r"(a.z), "r"(a.w), "r"(b.x), "r"(b.y));
}

__device__ __forceinline__ unsigned smem_u32(const void* p) {
    unsigned a;
    asm("{ .reg .u64 t; cvta.to.shared.u64 t, %1; cvt.u32.u64 %0, t; }"
        : "=r"(a) : "l"(p));
    return a;
}

__device__ __forceinline__ void cpa16(unsigned s, const void* g) {
    asm volatile("cp.async.cg.shared.global [%0], [%1], 16;" :: "r"(s), "l"(g));
}

// ---------------------------------------------------------------------------
// Kernel 1: global average pool (float4 loads).
// ---------------------------------------------------------------------------
__global__ void gap_kernel(const float* __restrict__ x) {
    int bc = blockIdx.x;
    const float4* p = (const float4*)(x + (size_t)bc * HW);   // 784 float4
    float s = 0.f;
    for (int i = threadIdx.x; i < HW/4; i += blockDim.x) {
        float4 v = p[i];
        s += (v.x + v.y) + (v.z + v.w);
    }
    __shared__ float red[8];
    for (int off = 16; off > 0; off >>= 1) s += __shfl_down_sync(0xffffffffu, s, off);
    int wid = threadIdx.x >> 5, lid = threadIdx.x & 31;
    if (lid == 0) red[wid] = s;
    __syncthreads();
    if (wid == 0) {
        s = (lid < (blockDim.x >> 5)) ? red[lid] : 0.f;
        for (int off = 4; off > 0; off >>= 1) s += __shfl_down_sync(0xffffffffu, s, off);
        if (lid == 0) g_pooled[bc] = s * (1.f / (float)HW);
    }
}

// ---------------------------------------------------------------------------
// Kernel 2: routing = sigmoid(pooled @ Wr^T + br).
// ---------------------------------------------------------------------------
__global__ void routing_kernel(const float* __restrict__ rw,
                               const float* __restrict__ rb) {
    int t = threadIdx.x;
    if (t >= B*E) return;
    int b = t >> 3, e = t & 7;
    float s = rb[e];
    const float* pp = &g_pooled[b*CIN];
    const float* wp = &rw[e*CIN];
    #pragma unroll 8
    for (int i = 0; i < CIN; i++) s = fmaf(pp[i], wp[i], s);
    g_route[t] = 1.f / (1.f + expf(-s));
}

// ---------------------------------------------------------------------------
// Kernel 3: combine experts -> frag-order fp16 weights, smem-staged.
// Grid (16 cic, 4 cot, 8 z) where z = tile*2 + cohalf. 256 threads.
// Block's element set: co = cot*64 + tile*16 + cohalf*8 + grp (grp 0..7),
//                      ci = cic*16 + [0..15], taps 0..8.
// Phase A: coalesced float4 loads of the 8e x 8co x 144 slab -> smem.
// Phase B: each thread produces output u32s (half2) at
//   idx = tap*512 + tile*128 + grp*16 + tg*4 + rrhigh*2 + cohalf,
//   enumerated so a warp spans a stride-2 window (coalesced-ish writes).
// Every kw element is read exactly once chip-wide.
// ---------------------------------------------------------------------------
__global__ void combine_kernel(const float* __restrict__ kw) {
    __shared__ float r[B*E];
    __shared__ float s_kw[E * 8 * 144];          // 9216 floats = 36.9 KB
    if (threadIdx.x < B*E) r[threadIdx.x] = g_route[threadIdx.x];

    const int cic    = blockIdx.x;   // 0..15
    const int cot    = blockIdx.y;   // 0..3
    const int tile   = blockIdx.z >> 1;   // 0..3
    const int cohalf = blockIdx.z & 1;    // 0..1
    const int co_base = cot * 64 + tile * 16 + cohalf * 8;

    // ---- Phase A: stage slab (float4: 2304 total, 9 per thread)
    #pragma unroll
    for (int k = 0; k < 9; k++) {
        int f4   = threadIdx.x + 256 * k;        // 0..2303
        int e    = f4 / 288;
        int rem  = f4 - e * 288;
        int grp  = rem / 36;
        int p4   = rem - grp * 36;
        const float4* src = (const float4*)(kw +
            ((size_t)(e * COUT + co_base + grp) * CIN + cic * CI_C) * TAPS) + p4;
        *(float4*)&s_kw[(e * 8 + grp) * 144 + p4 * 4] = *src;
    }
    __syncthreads();

    // ---- Phase B: combine + frag-order writes
    for (int pos = threadIdx.x; pos < 576; pos += 256) {
        // pos = ((tap*8 + grp)*4 + tg)*2 + rrhigh
        int rrhigh = pos & 1;
        int tg     = (pos >> 1) & 3;
        int grp    = (pos >> 3) & 7;
        int tap    = pos >> 6;
        int cie    = 2 * tg + 8 * rrhigh;        // local even ci
        int idx    = tap * 512 + tile * 128 + grp * 16 + tg * 4 + rrhigh * 2 + cohalf;

        float w0[E], w1[E];
        #pragma unroll
        for (int e = 0; e < E; e++) {
            const float* sp = &s_kw[(e * 8 + grp) * 144 + tap];
            w0[e] = sp[cie * TAPS];
            w1[e] = sp[(cie + 1) * TAPS];
        }
        unsigned* dst = g_cwf + ((size_t)cot * NCHUNK + cic) * CHUNK_W + idx;
        #pragma unroll
        for (int b = 0; b < B; b++) {
            float s0 = 0.f, s1 = 0.f;
            #pragma unroll
            for (int e = 0; e < E; e++) {
                float rv = r[b*E + e];
                s0 = fmaf(rv, w0[e], s0);
                s1 = fmaf(rv, w1[e], s1);
            }
            __half2 h = __floats2half2_rn(s0, s1);
            dst[(size_t)b * (4 * NCHUNK * CHUNK_W)] = *(unsigned*)&h;
        }
    }
}

// ---------------------------------------------------------------------------
// Kernel 3b: input prep -> g_xin[b][rq][cic][6*480], zero-padded, fp16,
// slot q = 2*tg+h -> ci pair {2tg+8h, 2tg+8h+1}. Smem transpose so both
// global reads and writes are coalesced.
// Grid (14 rq, 16 cic, 16 b), 256 threads.
// ---------------------------------------------------------------------------
__global__ void prep_kernel(const float* __restrict__ x) {
    const int rq = blockIdx.x, cic = blockIdx.y, b = blockIdx.z;
    const float* xb = x + (size_t)b * CIN * HW;
    __shared__ float s[CI_C * 6 * 61];           // padded stride 61

    // phase A: coalesced global reads
    for (int idx = threadIdx.x; idx < CI_C * 6 * 60; idx += 256) {
        int ci  = idx / 360;
        int rem = idx - ci * 360;
        int row = rem / 60;
        int col = rem - row * 60;
        int gr  = rq * RP + row - 1;
        int gc  = col - 1;
        float v = 0.f;
        if ((unsigned)gr < HH && (unsigned)gc < WW)
            v = xb[(cic * CI_C + ci) * HW + gr * WW + gc];
        s[(ci * 6 + row) * 61 + col] = v;
    }
    __syncthreads();

    // phase B: coalesced interleaved fp16 writes
    unsigned* dst = g_xin + ((size_t)(b * NRQ + rq) * NCHUNK + cic) * CHUNK_IN;
    for (int i = threadIdx.x; i < CHUNK_IN; i += 256) {
        int row = i / ROWU;
        int p   = i - row * ROWU;
        int col = p >> 3;
        int q   = p & 7;
        int ci0 = 2 * (q >> 1) + 8 * (q & 1);
        float f0 = s[((ci0    ) * 6 + row) * 61 + col];
        float f1 = s[((ci0 + 1) * 6 + row) * 61 + col];
        __half2 h = __floats2half2_rn(f0, f1);
        dst[i] = *(unsigned*)&h;
    }
}

// ---------------------------------------------------------------------------
// Kernel 4: fp16 tensor-core implicit conv + BN + SiLU.
// Double-buffered cp.async staging. CTA: (rq, cot, b), 128 thr = 4 warps.
// ---------------------------------------------------------------------------
__global__ __launch_bounds__(128, 3)
void conv_mma_kernel(const float* __restrict__ bn_gamma,
                     const float* __restrict__ bn_beta,
                     const float* __restrict__ bn_mean,
                     const float* __restrict__ bn_var,
                     float* __restrict__ out) {
    const int rq   = blockIdx.x;
    const int cot  = blockIdx.y;
    const int b    = blockIdx.z;
    const int co0  = cot * CO_T;
    const int row0 = rq * RP;

    const int tid  = threadIdx.x;
    const int lane = tid & 31;
    const int wid  = tid >> 5;
    const int tg   = lane & 3;
    const int grp  = lane >> 2;

    __shared__ __align__(16) unsigned s_in[2][CHUNK_IN];
    __shared__ __align__(16) unsigned s_w [2][CHUNK_W];

    const unsigned* gin = g_xin + (size_t)(b * NRQ + rq) * NCHUNK * CHUNK_IN;
    const unsigned* gw  = g_cwf + (size_t)(b * 4 + cot) * NCHUNK * CHUNK_W;

    float acc[4][7][4];
    #pragma unroll
    for (int t = 0; t < 4; t++)
        #pragma unroll
        for (int j = 0; j < 7; j++)
            #pragma unroll
            for (int q = 0; q < 4; q++) acc[t][j][q] = 0.f;

    auto stage = [&](int c, int sb) {
        unsigned din = smem_u32(&s_in[sb][0]);
        unsigned dw  = smem_u32(&s_w[sb][0]);
        const unsigned* src_in = gin + (size_t)c * CHUNK_IN;
        const unsigned* src_w  = gw  + (size_t)c * CHUNK_W;
        #pragma unroll
        for (int k = 0; k < 6; k++) {
            int i = tid + 128 * k;                 // 16B units, 720 total
            if (i < CHUNK_IN / 4)
                cpa16(din + 16u * i, src_in + 4 * i);
        }
        #pragma unroll
        for (int k = 0; k < 9; k++) {
            int i = tid + 128 * k;                 // 1152 total
            cpa16(dw + 16u * i, src_w + 4 * i);
        }
    };

    stage(0, 0);
    asm volatile("cp.async.commit_group;");

    for (int c = 0; c < NCHUNK; c++) {
        const int cur = c & 1;
        if (c + 1 < NCHUNK) stage(c + 1, cur ^ 1);
        asm volatile("cp.async.commit_group;");
        asm volatile("cp.async.wait_group 1;");
        __syncthreads();

        #pragma unroll
        for (int kh = 0; kh < 3; kh++) {
            const unsigned* brow = &s_in[cur][(wid + kh) * ROWU];
            #pragma unroll
            for (int kw3 = 0; kw3 < 3; kw3++) {
                const int tap = kh * 3 + kw3;
                uint4 a[4];
                #pragma unroll
                for (int t = 0; t < 4; t++)
                    a[t] = *(const uint4*)(&s_w[cur][(tap * 4 + t) * 128 + lane * 4]);
                uint2 bv[7];
                #pragma unroll
                for (int j = 0; j < 7; j++)
                    bv[j] = *(const uint2*)(&brow[(j * 8 + grp + kw3) * 8 + tg * 2]);
                #pragma unroll
                for (int t = 0; t < 4; t++)
                    #pragma unroll
                    for (int j = 0; j < 7; j++)
                        mma16(acc[t][j], a[t], bv[j]);
            }
        }
        __syncthreads();
    }

    // ---- epilogue: BN + SiLU, float2 stores
    const int orow = row0 + wid;
    #pragma unroll
    for (int t = 0; t < 4; t++) {
        const int c1 = co0 + t * 16 + grp;
        const int c2 = c1 + 8;
        const float inv1 = bn_gamma[c1] * rsqrtf(bn_var[c1] + BN_EPS);
        const float sh1  = bn_beta[c1] - bn_mean[c1] * inv1;
        const float inv2 = bn_gamma[c2] * rsqrtf(bn_var[c2] + BN_EPS);
        const float sh2  = bn_beta[c2] - bn_mean[c2] * inv2;
        float* o1 = out + ((size_t)(b * COUT + c1) * HH + orow) * WW;
        float* o2 = out + ((size_t)(b * COUT + c2) * HH + orow) * WW;
        #pragma unroll
        for (int j = 0; j < 7; j++) {
            int col = j * 8 + 2 * tg;
            float y0 = fmaf(acc[t][j][0], inv1, sh1);
            float y1 = fmaf(acc[t][j][1], inv1, sh1);
            float y2 = fmaf(acc[t][j][2], inv2, sh2);
            float y3 = fmaf(acc[t][j][3], inv2, sh2);
            float2 r1 = make_float2(y0 / (1.f + expf(-y0)), y1 / (1.f + expf(-y1)));
            float2 r2 = make_float2(y2 / (1.f + expf(-y2)), y3 / (1.f + expf(-y3)));
            *(float2*)(o1 + col) = r1;
            *(float2*)(o2 + col) = r2;
        }
    }
}

// ---------------------------------------------------------------------------
extern "C" void kernel_launch(void* const* d_in, const int* in_sizes, int n_in,
                              void* d_out, int out_size) {
    const float* x        = (const float*)d_in[0];
    const float* rw       = (const float*)d_in[1];
    const float* rb       = (const float*)d_in[2];
    const float* kw       = (const float*)d_in[3];
    const float* bn_gamma = (const float*)d_in[4];
    const float* bn_beta  = (const float*)d_in[5];
    const float* bn_mean  = (const float*)d_in[6];
    const float* bn_var   = (const float*)d_in[7];
    float* out = (float*)d_out;

    prep_kernel<<<dim3(NRQ, NCHUNK, B), 256>>>(x);
    gap_kernel<<<B*CIN, 256>>>(x);
    routing_kernel<<<1, 128>>>(rw, rb);
    combine_kernel<<<dim3(NCHUNK, 4, 8), 256>>>(kw);
    dim3 grid(NRQ, 4, B);                      // (14, 4, 16)
    conv_mma_kernel<<<grid, 128>>>(bn_gamma, bn_beta, bn_mean, bn_var, out);
}